// round 1
// baseline (speedup 1.0000x reference)
#include <cuda_runtime.h>
#include <cstdint>

#define Hh   128
#define Ww   240
#define NG   40
#define CPG  8
#define ND   48
#define NCC  12
#define WQ   (Ww / 4)   // 60 float4 chunks per row

__device__ __forceinline__ uint32_t sw128(uint32_t b) {
    // SW128 swizzle: XOR bits[6:4] with bits[9:7] — conflict-free LDS.128 at
    // 128B lane stride
    return b ^ ((b >> 3) & 0x70);
}

// ---------------------------------------------------------------------------
// GWC volume: out[g][d][h][w] = (1/8) * sum_c ref[g*8+c][h][w] * tgt[g*8+c][h][w-d]
// (zero when w < d). One CTA per (g, h). Threads own 4 consecutive w.
// Sliding register window over d: only 1 new tgt position (2 LDS.128) per d.
// ---------------------------------------------------------------------------
__global__ void __launch_bounds__(64) gwc_kernel(
    const float* __restrict__ refg, const float* __restrict__ tgtg,
    float* __restrict__ out)
{
    __shared__ __align__(16) unsigned char smem[Ww * 32];  // 240 w * 8c * 4B = 7680B

    const int g   = blockIdx.x;
    const int h   = blockIdx.y;
    const int tid = threadIdx.x;

    // Stage tgt group-row into SMEM, transposed [w][c], SW128-swizzled.
    {
        const float* base = tgtg + ((size_t)(g * CPG) * Hh + h) * Ww;
        for (int i = tid; i < CPG * WQ; i += 64) {
            int cc = i / WQ;
            int wq = i - cc * WQ;
            float4 v = *(const float4*)(base + (size_t)cc * Hh * Ww + 4 * wq);
            float vv[4] = {v.x, v.y, v.z, v.w};
#pragma unroll
            for (int j = 0; j < 4; j++) {
                uint32_t boff = (uint32_t)((4 * wq + j) * 32 + cc * 4);
                *(float*)(smem + sw128(boff)) = vv[j];
            }
        }
    }

    // Ref: 4 w x 8 c into registers (coalesced LDG.128), pre-scaled by 1/8.
    float rt[4][8];
    const int wq = tid;
    const bool active = (wq < WQ);
    if (active) {
        const float* base = refg + ((size_t)(g * CPG) * Hh + h) * Ww + 4 * wq;
#pragma unroll
        for (int cc = 0; cc < 8; cc++) {
            float4 v = *(const float4*)(base + (size_t)cc * Hh * Ww);
            rt[0][cc] = v.x * 0.125f;
            rt[1][cc] = v.y * 0.125f;
            rt[2][cc] = v.z * 0.125f;
            rt[3][cc] = v.w * 0.125f;
        }
    }
    __syncthreads();
    if (!active) return;

    // Window invariant: slot[(j - d) & 3] holds tgt[4wq + j - d][0..7]
    float4 win[4][2];
#pragma unroll
    for (int k = 0; k < 4; k++) {
        uint32_t b = (uint32_t)((4 * wq + k) * 32);
        win[k][0] = *(const float4*)(smem + sw128(b));
        win[k][1] = *(const float4*)(smem + sw128(b + 16));
    }

    float* outp = out + (((size_t)g * ND) * Hh + h) * Ww + 4 * wq;
#pragma unroll
    for (int d = 0; d < ND; d++) {
        float a[4];
#pragma unroll
        for (int j = 0; j < 4; j++) {
            const float4 t0 = win[(j - d) & 3][0];
            const float4 t1 = win[(j - d) & 3][1];
            a[j] = rt[j][0] * t0.x + rt[j][1] * t0.y + rt[j][2] * t0.z + rt[j][3] * t0.w
                 + rt[j][4] * t1.x + rt[j][5] * t1.y + rt[j][6] * t1.z + rt[j][7] * t1.w;
        }
        float4 o; o.x = a[0]; o.y = a[1]; o.z = a[2]; o.w = a[3];
        *(float4*)outp = o;
        outp += (size_t)Hh * Ww;

        if (d < ND - 1) {
            // Refill: slot that held the highest position gets the new lowest.
            int wp   = 4 * wq - d - 1;
            int slot = (3 - d) & 3;
            if (wp >= 0) {
                uint32_t b = (uint32_t)(wp * 32);
                win[slot][0] = *(const float4*)(smem + sw128(b));
                win[slot][1] = *(const float4*)(smem + sw128(b + 16));
            } else {
                win[slot][0] = make_float4(0.f, 0.f, 0.f, 0.f);
                win[slot][1] = make_float4(0.f, 0.f, 0.f, 0.f);
            }
        }
    }
}

// ---------------------------------------------------------------------------
// Concat volume: channels 40..51 = ref_concat masked (w>=d),
//                channels 52..63 = tgt_concat shifted right by d.
// One CTA per (h, d); thread owns 4 consecutive w, loops over 12 channels.
// ---------------------------------------------------------------------------
__global__ void __launch_bounds__(64) concat_kernel(
    const float* __restrict__ rc, const float* __restrict__ tc,
    float* __restrict__ out)
{
    const int h  = blockIdx.x;
    const int d  = blockIdx.y;
    const int wq = threadIdx.x;
    if (wq >= WQ) return;
    const int wb = 4 * wq;

    const size_t chan_stride = (size_t)ND * Hh * Ww;
    float* ob = out + (((size_t)NG * ND + (size_t)d) * Hh + h) * Ww + wb;

#pragma unroll
    for (int c = 0; c < NCC; c++) {
        float4 v = *(const float4*)(rc + ((size_t)c * Hh + h) * Ww + wb);
        float4 o;
        o.x = (wb + 0 >= d) ? v.x : 0.f;
        o.y = (wb + 1 >= d) ? v.y : 0.f;
        o.z = (wb + 2 >= d) ? v.z : 0.f;
        o.w = (wb + 3 >= d) ? v.w : 0.f;
        *(float4*)(ob + (size_t)c * chan_stride) = o;
    }

    float* ob2 = ob + (size_t)NCC * chan_stride;
#pragma unroll
    for (int c = 0; c < NCC; c++) {
        const float* src = tc + ((size_t)c * Hh + h) * Ww;
        float4 o;
        o.x = (wb + 0 - d >= 0) ? __ldg(src + wb + 0 - d) : 0.f;
        o.y = (wb + 1 - d >= 0) ? __ldg(src + wb + 1 - d) : 0.f;
        o.z = (wb + 2 - d >= 0) ? __ldg(src + wb + 2 - d) : 0.f;
        o.w = (wb + 3 - d >= 0) ? __ldg(src + wb + 3 - d) : 0.f;
        *(float4*)(ob2 + (size_t)c * chan_stride) = o;
    }
}

extern "C" void kernel_launch(void* const* d_in, const int* in_sizes, int n_in,
                              void* d_out, int out_size)
{
    const float* refg = (const float*)d_in[0];  // ref_gwc    [320,128,240]
    const float* tgtg = (const float*)d_in[1];  // tgt_gwc    [320,128,240]
    const float* rc   = (const float*)d_in[2];  // ref_concat [12,128,240]
    const float* tc   = (const float*)d_in[3];  // tgt_concat [12,128,240]
    float* out = (float*)d_out;                 // [64,48,128,240]

    gwc_kernel<<<dim3(NG, Hh), 64>>>(refg, tgtg, out);
    concat_kernel<<<dim3(Hh, ND), 64>>>(rc, tc, out);
}